// round 12
// baseline (speedup 1.0000x reference)
#include <cuda_runtime.h>
#include <cuda_fp16.h>
#include <math.h>

#define Bq 4
#define Nq 4096
#define Hq 8
#define Dq 64
#define Mq 64
#define SEG 32
#define BH  (Bq*Hq)
#define P2  72          // smem row pitch in halves (144B: 16B-aligned, ldmatrix conflict-free)
#define ONESH2 0x3C003C00u   // half2(1.0, 1.0)

// Global accumulators (zeroed by zero_kernel each launch; graph-replay safe)
__device__ float g_KV[BH*Dq*Mq];
__device__ float g_Ksum[BH*Dq];

__device__ __forceinline__ float fmap(float x) {
    return x > 0.0f ? x + 1.0f : __expf(x);   // elu(x)+1
}
__device__ __forceinline__ unsigned pack_h2(float lo, float hi) {
    __half2 h = __floats2half2_rn(lo, hi);
    return *reinterpret_cast<unsigned*>(&h);
}
__device__ __forceinline__ void mma_fp16(float4& d,
                                         unsigned a0, unsigned a1, unsigned a2, unsigned a3,
                                         unsigned b0, unsigned b1) {
    asm volatile(
        "mma.sync.aligned.m16n8k16.row.col.f32.f16.f16.f32 "
        "{%0,%1,%2,%3}, {%4,%5,%6,%7}, {%8,%9}, {%0,%1,%2,%3};"
        : "+f"(d.x), "+f"(d.y), "+f"(d.z), "+f"(d.w)
        : "r"(a0), "r"(a1), "r"(a2), "r"(a3), "r"(b0), "r"(b1));
}
__device__ __forceinline__ void ldm_x4t(unsigned& r0, unsigned& r1, unsigned& r2, unsigned& r3,
                                        unsigned addr) {
    asm volatile("ldmatrix.sync.aligned.m8n8.x4.trans.shared.b16 {%0,%1,%2,%3}, [%4];"
        : "=r"(r0), "=r"(r1), "=r"(r2), "=r"(r3) : "r"(addr));
}
__device__ __forceinline__ void ldm_x4(unsigned& r0, unsigned& r1, unsigned& r2, unsigned& r3,
                                       unsigned addr) {
    asm volatile("ldmatrix.sync.aligned.m8n8.x4.shared.b16 {%0,%1,%2,%3}, [%4];"
        : "=r"(r0), "=r"(r1), "=r"(r2), "=r"(r3) : "r"(addr));
}
__device__ __forceinline__ void ldm_x2t(unsigned& r0, unsigned& r1, unsigned addr) {
    asm volatile("ldmatrix.sync.aligned.m8n8.x2.trans.shared.b16 {%0,%1}, [%2];"
        : "=r"(r0), "=r"(r1) : "r"(addr));
}

__global__ void __launch_bounds__(256) zero_kernel() {
    const int i = blockIdx.x * 256 + threadIdx.x;
    if (i < BH * Dq * Mq) g_KV[i] = 0.0f;
    if (i < BH * Dq)      g_Ksum[i] = 0.0f;
}

// ============ pass1: g_KV[bh] += fmap(K)^T V over this seg's 128 rows (REDG atomics) ============
// grid (SEG, H, B) = 1024 blocks, 256 thr (8 warps), min 4 blocks/SM.
// 2 chunks of 64 rows, double-buffered smem, register-prefetch pipeline.
// Warp w: d-strip = w&3 (16 d), m j-tiles 4*(w>>2)..+3 (32 m).
// Ksum folded into MMA with B = ones (warps 0-3 only).
__global__ void __launch_bounds__(256, 4) pass1_kernel(const float* __restrict__ Kp,
                                                       const float* __restrict__ Vp) {
    __shared__ __align__(16) __half Ksm[2][64][P2];
    __shared__ __align__(16) __half Vsm[2][64][P2];

    const int b = blockIdx.z, h = blockIdx.y, seg = blockIdx.x;
    const int bh = b * Hq + h;
    const int tid = threadIdx.x;
    const int w = tid >> 5, lane = tid & 31;
    const int gid = lane >> 2, tig = lane & 3;
    const int strip = w & 3;          // d-strip (16 d-rows)
    const int jt0 = (w >> 2) * 4;     // first m j-tile (of 4)
    const int n0 = seg * 128;

    const int g = lane >> 3, r = lane & 7;
    const int arow_off = ((g >> 1) ? 8 : 0) + r;   // A (trans, x4)
    const int acol_off = (g & 1) ? 8 : 0;
    const int brow_off = ((g & 1) ? 8 : 0) + r;    // B (trans, x2)

    // hoisted base pointers; row stride = Hq*Dq = Hq*Mq = 512 floats
    const float* kp = Kp + ((size_t)(b * Nq + n0) * Hq + h) * Dq;
    const float* vp = Vp + ((size_t)(b * Nq + n0) * Hq + h) * Mq;
    const int nrow = tid >> 4, c4 = tid & 15;   // 4 staging jobs/chunk: n = i*16+nrow

    float4 kreg[4], vreg[4];
    // prefetch chunk 0
    #pragma unroll
    for (int i = 0; i < 4; i++) {
        const int n = i * 16 + nrow;
        kreg[i] = *(const float4*)(kp + (size_t)n * 512 + c4 * 4);
        vreg[i] = *(const float4*)(vp + (size_t)n * 512 + c4 * 4);
    }

    float4 acc[4];
    #pragma unroll
    for (int j = 0; j < 4; j++) acc[j] = make_float4(0.f, 0.f, 0.f, 0.f);
    float4 accK = make_float4(0.f, 0.f, 0.f, 0.f);   // Ksum accumulator (warps 0-3)

    const int d0 = 16 * strip;
    #pragma unroll
    for (int c = 0; c < 2; c++) {
        const int buf = c;
        // convert + STS current chunk from regs
        #pragma unroll
        for (int i = 0; i < 4; i++) {
            const int n = i * 16 + nrow;
            uint2 ku, vu;
            ku.x = pack_h2(fmap(kreg[i].x), fmap(kreg[i].y));
            ku.y = pack_h2(fmap(kreg[i].z), fmap(kreg[i].w));
            *(uint2*)&Ksm[buf][n][c4 * 4] = ku;
            vu.x = pack_h2(vreg[i].x, vreg[i].y);
            vu.y = pack_h2(vreg[i].z, vreg[i].w);
            *(uint2*)&Vsm[buf][n][c4 * 4] = vu;
        }
        // prefetch next chunk — LDG in flight during the MMA below
        if (c == 0) {
            #pragma unroll
            for (int i = 0; i < 4; i++) {
                const int n = 64 + i * 16 + nrow;
                kreg[i] = *(const float4*)(kp + (size_t)n * 512 + c4 * 4);
                vreg[i] = *(const float4*)(vp + (size_t)n * 512 + c4 * 4);
            }
        }
        __syncthreads();

        const unsigned Kbase = (unsigned)__cvta_generic_to_shared(&Ksm[buf][0][0]);
        const unsigned Vbase = (unsigned)__cvta_generic_to_shared(&Vsm[buf][0][0]);
        #pragma unroll
        for (int ks = 0; ks < 4; ks++) {
            const int k0 = ks * 16;
            unsigned a0, a1, a2, a3;
            const unsigned aaddr = Kbase +
                ((unsigned)((k0 + arow_off) * P2 + d0 + acol_off)) * 2u;
            ldm_x4t(a0, a1, a2, a3, aaddr);
            if (w < 4)   // Ksum = K'^T @ ones
                mma_fp16(accK, a0, a1, a2, a3, ONESH2, ONESH2);
            #pragma unroll
            for (int j = 0; j < 4; j++) {
                const int m0 = 8 * (jt0 + j);
                unsigned b0, b1;
                const unsigned baddr = Vbase +
                    ((unsigned)((k0 + brow_off) * P2 + m0)) * 2u;
                ldm_x2t(b0, b1, baddr);
                mma_fp16(acc[j], a0, a1, a2, a3, b0, b1);
            }
        }
    }

    // epilogue: fire-and-forget atomic accumulation (no scratch round-trip)
    float* kv = g_KV + (size_t)bh * Dq * Mq;
    const int d = d0 + gid;
    #pragma unroll
    for (int j = 0; j < 4; j++) {
        const int m = 8 * (jt0 + j) + 2 * tig;
        atomicAdd(&kv[d * Mq + m],           acc[j].x);
        atomicAdd(&kv[d * Mq + m + 1],       acc[j].y);
        atomicAdd(&kv[(d + 8) * Mq + m],     acc[j].z);
        atomicAdd(&kv[(d + 8) * Mq + m + 1], acc[j].w);
    }
    if (w < 4 && tig == 0) {   // col 0 of the ones-MMA = Ksum strip
        atomicAdd(&g_Ksum[bh * Dq + d0 + gid],     accK.x);
        atomicAdd(&g_Ksum[bh * Dq + d0 + gid + 8], accK.z);
    }
}

// ============ pass2: out = Z * fmap(Q) @ KV ============
// grid (64, H, B) = 2048 blocks, 256 thr (8 warps), min 4 blocks/SM. 64 n-rows/block;
// inter-block wave overlap hides staging latency.
// Warp w: n-strip = w&3 (16 rows), m j-tiles 4*(w>>2)..+3.
// Z folded into MMA with B = Ksum fragments.
__global__ void __launch_bounds__(256, 4) pass2_kernel(const float* __restrict__ Qp,
                                                       float* __restrict__ Op) {
    __shared__ __align__(16) __half Qsm[64][P2];    // [n][d]
    __shared__ __align__(16) __half KVsm[64][P2];   // [d][m]
    __shared__ float Kss[64];

    const int b = blockIdx.z, h = blockIdx.y;
    const int bh = b * Hq + h;
    const int n0 = blockIdx.x * 64;
    const int tid = threadIdx.x;
    const int w = tid >> 5, lane = tid & 31;
    const int gid = lane >> 2, tig = lane & 3;
    const int strip = w & 3;
    const int jt0 = (w >> 2) * 4;

    const unsigned Qbase  = (unsigned)__cvta_generic_to_shared(&Qsm[0][0]);
    const unsigned KVbase = (unsigned)__cvta_generic_to_shared(&KVsm[0][0]);
    const int g = lane >> 3, r = lane & 7;
    const int arow_off = ((g & 1) ? 8 : 0) + r;    // A (non-trans, x4)
    const int acol_off = (g >> 1) ? 8 : 0;
    const int brow_off = ((g & 1) ? 8 : 0) + r;    // B (trans, x2)

    const float* kvg = g_KV + (size_t)bh * Dq * Mq;
    const float* qp  = Qp + ((size_t)(b * Nq + n0) * Hq + h) * Dq;
    const int nrow = tid >> 4, c4 = tid & 15;

    // staging: Q (4 jobs) + KV (4 jobs, L2-resident) + Ksum
    #pragma unroll
    for (int it = 0; it < 4; it++) {
        const int rr = it * 16 + nrow;
        const float4 q = *(const float4*)(qp + (size_t)rr * 512 + c4 * 4);
        uint2 qu;
        qu.x = pack_h2(fmap(q.x), fmap(q.y));
        qu.y = pack_h2(fmap(q.z), fmap(q.w));
        *(uint2*)&Qsm[rr][c4 * 4] = qu;

        const float4 t = *(const float4*)(kvg + (size_t)rr * Mq + c4 * 4);
        uint2 tu;
        tu.x = pack_h2(t.x, t.y);
        tu.y = pack_h2(t.z, t.w);
        *(uint2*)&KVsm[rr][c4 * 4] = tu;
    }
    if (tid < 64) Kss[tid] = g_Ksum[bh * Dq + tid];
    __syncthreads();

    float4 acc[4];
    #pragma unroll
    for (int j = 0; j < 4; j++) acc[j] = make_float4(0.f, 0.f, 0.f, 0.f);
    float4 accZ = make_float4(0.f, 0.f, 0.f, 0.f);

    const int nr0 = 16 * strip;
    #pragma unroll
    for (int ks = 0; ks < 4; ks++) {
        const int k0 = ks * 16;
        unsigned a0, a1, a2, a3;
        const unsigned aaddr = Qbase +
            ((unsigned)((nr0 + arow_off) * P2 + k0 + acol_off)) * 2u;
        ldm_x4(a0, a1, a2, a3, aaddr);
        // Z fragment: B[k][n] = Kss[k] broadcast over n
        const unsigned zb0 = pack_h2(Kss[k0 + 2 * tig],     Kss[k0 + 2 * tig + 1]);
        const unsigned zb1 = pack_h2(Kss[k0 + 2 * tig + 8], Kss[k0 + 2 * tig + 9]);
        mma_fp16(accZ, a0, a1, a2, a3, zb0, zb1);
        #pragma unroll
        for (int j = 0; j < 4; j++) {
            const int m0 = 8 * (jt0 + j);
            unsigned b0, b1;
            const unsigned baddr = KVbase +
                ((unsigned)((k0 + brow_off) * P2 + m0)) * 2u;
            ldm_x2t(b0, b1, baddr);
            mma_fp16(acc[j], a0, a1, a2, a3, b0, b1);
        }
    }

    // per-lane normalizers from the Z-tile
    const float z0 = 1.0f / (accZ.x + 1e-6f);
    const float z1 = 1.0f / (accZ.z + 1e-6f);

    // epilogue: scale by Z, store
    const int row = nr0 + gid;
    float* op0 = Op + ((size_t)(b * Nq + n0 + row) * Hq + h) * Mq;
    float* op1 = op0 + (size_t)8 * Hq * Mq;
    #pragma unroll
    for (int j = 0; j < 4; j++) {
        const int m = 8 * (jt0 + j) + 2 * tig;
        *(float2*)(op0 + m) = make_float2(acc[j].x * z0, acc[j].y * z0);
        *(float2*)(op1 + m) = make_float2(acc[j].z * z1, acc[j].w * z1);
    }
}

extern "C" void kernel_launch(void* const* d_in, const int* in_sizes, int n_in,
                              void* d_out, int out_size) {
    const float* Q = (const float*)d_in[0];
    const float* K = (const float*)d_in[1];
    const float* V = (const float*)d_in[2];
    float* out = (float*)d_out;

    zero_kernel<<<512, 256>>>();
    pass1_kernel<<<dim3(SEG, Hq, Bq), 256>>>(K, V);
    pass2_kernel<<<dim3(64, Hq, Bq), 256>>>(Q, out);
}

// round 14
// speedup vs baseline: 1.0369x; 1.0369x over previous
#include <cuda_runtime.h>
#include <cuda_fp16.h>
#include <math.h>

#define Bq 4
#define Nq 4096
#define Hq 8
#define Dq 64
#define Mq 64
#define SEG 32
#define BH  (Bq*Hq)
#define P2  72          // smem row pitch in halves (144B: 16B-aligned, ldmatrix conflict-free)
#define ONESH2 0x3C003C00u   // half2(1.0, 1.0)
#define KVW (Dq*Mq/2)   // half2 words per bh KV tile (2048)

// Scratch (fully written each launch; fp16 partials)
__device__ __half2 g_KVp[SEG*BH*KVW];   // partial KV [seg][bh][d][m/2]
__device__ float   g_Ksp[SEG*BH*Dq];    // partial Ksum (fp32, tiny)
__device__ __half2 g_KVh[BH*KVW];       // reduced KV, fp16 (pass2-ready)
__device__ float   g_Ksum[BH*Dq];

__device__ __forceinline__ float fmap(float x) {
    return x > 0.0f ? x + 1.0f : __expf(x);   // elu(x)+1
}
__device__ __forceinline__ unsigned pack_h2(float lo, float hi) {
    __half2 h = __floats2half2_rn(lo, hi);
    return *reinterpret_cast<unsigned*>(&h);
}
__device__ __forceinline__ void mma_fp16(float4& d,
                                         unsigned a0, unsigned a1, unsigned a2, unsigned a3,
                                         unsigned b0, unsigned b1) {
    asm volatile(
        "mma.sync.aligned.m16n8k16.row.col.f32.f16.f16.f32 "
        "{%0,%1,%2,%3}, {%4,%5,%6,%7}, {%8,%9}, {%0,%1,%2,%3};"
        : "+f"(d.x), "+f"(d.y), "+f"(d.z), "+f"(d.w)
        : "r"(a0), "r"(a1), "r"(a2), "r"(a3), "r"(b0), "r"(b1));
}
__device__ __forceinline__ void ldm_x4t(unsigned& r0, unsigned& r1, unsigned& r2, unsigned& r3,
                                        unsigned addr) {
    asm volatile("ldmatrix.sync.aligned.m8n8.x4.trans.shared.b16 {%0,%1,%2,%3}, [%4];"
        : "=r"(r0), "=r"(r1), "=r"(r2), "=r"(r3) : "r"(addr));
}
__device__ __forceinline__ void ldm_x4(unsigned& r0, unsigned& r1, unsigned& r2, unsigned& r3,
                                       unsigned addr) {
    asm volatile("ldmatrix.sync.aligned.m8n8.x4.shared.b16 {%0,%1,%2,%3}, [%4];"
        : "=r"(r0), "=r"(r1), "=r"(r2), "=r"(r3) : "r"(addr));
}
__device__ __forceinline__ void ldm_x2t(unsigned& r0, unsigned& r1, unsigned addr) {
    asm volatile("ldmatrix.sync.aligned.m8n8.x2.trans.shared.b16 {%0,%1}, [%2];"
        : "=r"(r0), "=r"(r1) : "r"(addr));
}

// ============ pass1: KV_partial[seg][bh] = fmap(K)^T V over this seg's 128 rows ============
// grid (SEG, H, B) = 1024 blocks, 256 thr (8 warps), min 4 blocks/SM.
// 2 chunks of 64 rows, double-buffered smem, register-prefetch pipeline.
// Warp w: d-strip = w&3 (16 d), m j-tiles 4*(w>>2)..+3 (32 m).
// Ksum folded into MMA with B = ones (warps 0-3 only). Partials stored fp16.
__global__ void __launch_bounds__(256, 4) pass1_kernel(const float* __restrict__ Kp,
                                                       const float* __restrict__ Vp) {
    __shared__ __align__(16) __half Ksm[2][64][P2];
    __shared__ __align__(16) __half Vsm[2][64][P2];

    const int b = blockIdx.z, h = blockIdx.y, seg = blockIdx.x;
    const int bh = b * Hq + h;
    const int tid = threadIdx.x;
    const int w = tid >> 5, lane = tid & 31;
    const int gid = lane >> 2, tig = lane & 3;
    const int strip = w & 3;          // d-strip (16 d-rows)
    const int jt0 = (w >> 2) * 4;     // first m j-tile (of 4)
    const int n0 = seg * 128;

    const int g = lane >> 3, r = lane & 7;
    const int arow_off = ((g >> 1) ? 8 : 0) + r;   // A (trans, x4)
    const int acol_off = (g & 1) ? 8 : 0;
    const int brow_off = ((g & 1) ? 8 : 0) + r;    // B (trans, x2)

    // hoisted base pointers; row stride = Hq*Dq = Hq*Mq = 512 floats
    const float* kp = Kp + ((size_t)(b * Nq + n0) * Hq + h) * Dq;
    const float* vp = Vp + ((size_t)(b * Nq + n0) * Hq + h) * Mq;
    const int nrow = tid >> 4, c4 = tid & 15;   // 4 staging jobs/chunk: n = i*16+nrow

    float4 kreg[4], vreg[4];
    // prefetch chunk 0
    #pragma unroll
    for (int i = 0; i < 4; i++) {
        const int n = i * 16 + nrow;
        kreg[i] = *(const float4*)(kp + (size_t)n * 512 + c4 * 4);
        vreg[i] = *(const float4*)(vp + (size_t)n * 512 + c4 * 4);
    }

    float4 acc[4];
    #pragma unroll
    for (int j = 0; j < 4; j++) acc[j] = make_float4(0.f, 0.f, 0.f, 0.f);
    float4 accK = make_float4(0.f, 0.f, 0.f, 0.f);   // Ksum accumulator (warps 0-3)

    const int d0 = 16 * strip;
    #pragma unroll
    for (int c = 0; c < 2; c++) {
        const int buf = c;
        // convert + STS current chunk from regs
        #pragma unroll
        for (int i = 0; i < 4; i++) {
            const int n = i * 16 + nrow;
            uint2 ku, vu;
            ku.x = pack_h2(fmap(kreg[i].x), fmap(kreg[i].y));
            ku.y = pack_h2(fmap(kreg[i].z), fmap(kreg[i].w));
            *(uint2*)&Ksm[buf][n][c4 * 4] = ku;
            vu.x = pack_h2(vreg[i].x, vreg[i].y);
            vu.y = pack_h2(vreg[i].z, vreg[i].w);
            *(uint2*)&Vsm[buf][n][c4 * 4] = vu;
        }
        // prefetch next chunk — LDG in flight during the MMA below
        if (c == 0) {
            #pragma unroll
            for (int i = 0; i < 4; i++) {
                const int n = 64 + i * 16 + nrow;
                kreg[i] = *(const float4*)(kp + (size_t)n * 512 + c4 * 4);
                vreg[i] = *(const float4*)(vp + (size_t)n * 512 + c4 * 4);
            }
        }
        __syncthreads();

        const unsigned Kbase = (unsigned)__cvta_generic_to_shared(&Ksm[buf][0][0]);
        const unsigned Vbase = (unsigned)__cvta_generic_to_shared(&Vsm[buf][0][0]);
        #pragma unroll
        for (int ks = 0; ks < 4; ks++) {
            const int k0 = ks * 16;
            unsigned a0, a1, a2, a3;
            const unsigned aaddr = Kbase +
                ((unsigned)((k0 + arow_off) * P2 + d0 + acol_off)) * 2u;
            ldm_x4t(a0, a1, a2, a3, aaddr);
            if (w < 4)   // Ksum = K'^T @ ones
                mma_fp16(accK, a0, a1, a2, a3, ONESH2, ONESH2);
            #pragma unroll
            for (int j = 0; j < 4; j++) {
                const int m0 = 8 * (jt0 + j);
                unsigned b0, b1;
                const unsigned baddr = Vbase +
                    ((unsigned)((k0 + brow_off) * P2 + m0)) * 2u;
                ldm_x2t(b0, b1, baddr);
                mma_fp16(acc[j], a0, a1, a2, a3, b0, b1);
            }
        }
    }

    // epilogue: write fp16 partial KV (block exclusively owns [seg][bh])
    __half2* kv = g_KVp + ((size_t)seg * BH + bh) * KVW;
    const int d = d0 + gid;
    #pragma unroll
    for (int j = 0; j < 4; j++) {
        const int m = 8 * (jt0 + j) + 2 * tig;   // even
        kv[(d * Mq + m) >> 1]       = __floats2half2_rn(acc[j].x, acc[j].y);
        kv[((d + 8) * Mq + m) >> 1] = __floats2half2_rn(acc[j].z, acc[j].w);
    }
    if (w < 4 && tig == 0) {   // col 0 of the ones-MMA = Ksum strip
        float* kss = g_Ksp + ((size_t)seg * BH + bh) * Dq;
        kss[d0 + gid]     = accK.x;
        kss[d0 + gid + 8] = accK.z;
    }
}

// ============ reduce: sum SEG fp16 partials -> fp16 KV + fp32 Ksum ============
// BH*KVW = 65536 half2 positions; 256 blocks x 256 thr.
__global__ void __launch_bounds__(256) reduce_kernel() {
    const int i = blockIdx.x * 256 + threadIdx.x;
    if (i < BH * KVW) {
        float sx = 0.0f, sy = 0.0f;
        #pragma unroll
        for (int sg = 0; sg < SEG; sg++) {
            const float2 f = __half22float2(g_KVp[(size_t)sg * BH * KVW + i]);
            sx += f.x; sy += f.y;
        }
        g_KVh[i] = __floats2half2_rn(sx, sy);
    }
    if (i < BH * Dq) {
        float s = 0.0f;
        #pragma unroll
        for (int sg = 0; sg < SEG; sg++) s += g_Ksp[sg * BH * Dq + i];
        g_Ksum[i] = s;
    }
}

// ============ pass2: out = Z * fmap(Q) @ KV ============
// grid (64, H, B) = 2048 blocks, 256 thr (8 warps), min 4 blocks/SM. 64 n-rows/block.
// Warp w: n-strip = w&3 (16 rows), m j-tiles 4*(w>>2)..+3.
// Z folded into MMA with B = Ksum fragments. KV staged as raw fp16 uint4 copy.
__global__ void __launch_bounds__(256, 4) pass2_kernel(const float* __restrict__ Qp,
                                                       float* __restrict__ Op) {
    __shared__ __align__(16) __half Qsm[64][P2];    // [n][d]
    __shared__ __align__(16) __half KVsm[64][P2];   // [d][m]
    __shared__ float Kss[64];

    const int b = blockIdx.z, h = blockIdx.y;
    const int bh = b * Hq + h;
    const int n0 = blockIdx.x * 64;
    const int tid = threadIdx.x;
    const int w = tid >> 5, lane = tid & 31;
    const int gid = lane >> 2, tig = lane & 3;
    const int strip = w & 3;
    const int jt0 = (w >> 2) * 4;

    const unsigned Qbase  = (unsigned)__cvta_generic_to_shared(&Qsm[0][0]);
    const unsigned KVbase = (unsigned)__cvta_generic_to_shared(&KVsm[0][0]);
    const int g = lane >> 3, r = lane & 7;
    const int arow_off = ((g & 1) ? 8 : 0) + r;    // A (non-trans, x4)
    const int acol_off = (g >> 1) ? 8 : 0;
    const int brow_off = ((g & 1) ? 8 : 0) + r;    // B (trans, x2)

    const float* qp = Qp + ((size_t)(b * Nq + n0) * Hq + h) * Dq;
    const int nrow = tid >> 4, c4 = tid & 15;

    // KV staging: raw 16-byte copy of fp16 tile.
    // 512 uint4 jobs x 8 halves = 4096 halves = full 64x64 tile.
    // job -> row = job>>3, cols = (job&7)*8 .. +7  (matches source uint4 layout)
    const uint4* kvsrc = (const uint4*)(g_KVh + (size_t)bh * KVW);
    #pragma unroll
    for (int it = 0; it < 2; it++) {
        const int job = it * 256 + tid;          // 0..511
        const int rr = job >> 3, cc = job & 7;   // row, 8-half chunk
        *(uint4*)&KVsm[rr][cc * 8] = kvsrc[job];
    }
    // Q staging (fmap + convert)
    #pragma unroll
    for (int it = 0; it < 4; it++) {
        const int rr = it * 16 + nrow;
        const float4 q = *(const float4*)(qp + (size_t)rr * 512 + c4 * 4);
        uint2 qu;
        qu.x = pack_h2(fmap(q.x), fmap(q.y));
        qu.y = pack_h2(fmap(q.z), fmap(q.w));
        *(uint2*)&Qsm[rr][c4 * 4] = qu;
    }
    if (tid < 64) Kss[tid] = g_Ksum[bh * Dq + tid];
    __syncthreads();

    float4 acc[4];
    #pragma unroll
    for (int j = 0; j < 4; j++) acc[j] = make_float4(0.f, 0.f, 0.f, 0.f);
    float4 accZ = make_float4(0.f, 0.f, 0.f, 0.f);

    const int nr0 = 16 * strip;
    #pragma unroll
    for (int ks = 0; ks < 4; ks++) {
        const int k0 = ks * 16;
        unsigned a0, a1, a2, a3;
        const unsigned aaddr = Qbase +
            ((unsigned)((nr0 + arow_off) * P2 + k0 + acol_off)) * 2u;
        ldm_x4(a0, a1, a2, a3, aaddr);
        // Z fragment: B[k][n] = Kss[k] broadcast over n
        const unsigned zb0 = pack_h2(Kss[k0 + 2 * tig],     Kss[k0 + 2 * tig + 1]);
        const unsigned zb1 = pack_h2(Kss[k0 + 2 * tig + 8], Kss[k0 + 2 * tig + 9]);
        mma_fp16(accZ, a0, a1, a2, a3, zb0, zb1);
        #pragma unroll
        for (int j = 0; j < 4; j++) {
            const int m0 = 8 * (jt0 + j);
            unsigned b0, b1;
            const unsigned baddr = KVbase +
                ((unsigned)((k0 + brow_off) * P2 + m0)) * 2u;
            ldm_x2t(b0, b1, baddr);
            mma_fp16(acc[j], a0, a1, a2, a3, b0, b1);
        }
    }

    // per-lane normalizers from the Z-tile
    const float z0 = 1.0f / (accZ.x + 1e-6f);
    const float z1 = 1.0f / (accZ.z + 1e-6f);

    // epilogue: scale by Z, store
    const int row = nr0 + gid;
    float* op0 = Op + ((size_t)(b * Nq + n0 + row) * Hq + h) * Mq;
    float* op1 = op0 + (size_t)8 * Hq * Mq;
    #pragma unroll
    for (int j = 0; j < 4; j++) {
        const int m = 8 * (jt0 + j) + 2 * tig;
        *(float2*)(op0 + m) = make_float2(acc[j].x * z0, acc[j].y * z0);
        *(float2*)(op1 + m) = make_float2(acc[j].z * z1, acc[j].w * z1);
    }
}

extern "C" void kernel_launch(void* const* d_in, const int* in_sizes, int n_in,
                              void* d_out, int out_size) {
    const float* Q = (const float*)d_in[0];
    const float* K = (const float*)d_in[1];
    const float* V = (const float*)d_in[2];
    float* out = (float*)d_out;

    pass1_kernel<<<dim3(SEG, Hq, Bq), 256>>>(K, V);
    reduce_kernel<<<256, 256>>>();
    pass2_kernel<<<dim3(64, Hq, Bq), 256>>>(Q, out);
}